// round 1
// baseline (speedup 1.0000x reference)
#include <cuda_runtime.h>

#define D       128
#define D4      32          // D/4 float4s per row
#define N_MAX   100000
#define E_MAX   3200000
#define EPSV    1e-5f

// ---------------- scratch (static device globals; no runtime allocation) ---
__device__ int   g_deg[N_MAX];
__device__ int   g_row[N_MAX + 1];
__device__ int   g_cur[N_MAX];
__device__ int   g_csr[E_MAX];
__device__ float g_mean[(size_t)N_MAX * D];
__device__ float g_h[(size_t)N_MAX * D];
__device__ float g_colsum[D];
__device__ float g_colsum2[D];
__device__ float g_scale[D];
__device__ float g_shift[D];

// ---------------- 1. zero the per-call accumulators ------------------------
__global__ void zero_kernel(int n) {
    int i = blockIdx.x * blockDim.x + threadIdx.x;
    if (i < n) g_deg[i] = 0;
    if (i < D) { g_colsum[i] = 0.f; g_colsum2[i] = 0.f; }
}

// ---------------- 2. degree histogram --------------------------------------
__global__ void hist_kernel(const int* __restrict__ dst, int e) {
    int i = blockIdx.x * blockDim.x + threadIdx.x;
    if (i < e) atomicAdd(&g_deg[dst[i]], 1);
}

// ---------------- 3. exclusive scan (single block, 1024 thr) ---------------
__global__ void scan_kernel(int n) {
    __shared__ int warpsums[32];
    __shared__ int s_carry;
    int tid = threadIdx.x, lane = tid & 31, wid = tid >> 5;
    if (tid == 0) s_carry = 0;
    __syncthreads();
    for (int base = 0; base < n; base += 1024) {
        int i = base + tid;
        int v = (i < n) ? g_deg[i] : 0;
        int incl = v;
        #pragma unroll
        for (int off = 1; off < 32; off <<= 1) {
            int t = __shfl_up_sync(0xffffffffu, incl, off);
            if (lane >= off) incl += t;
        }
        if (lane == 31) warpsums[wid] = incl;
        __syncthreads();
        if (wid == 0) {
            int s = warpsums[lane];
            #pragma unroll
            for (int off = 1; off < 32; off <<= 1) {
                int t = __shfl_up_sync(0xffffffffu, s, off);
                if (lane >= off) s += t;
            }
            warpsums[lane] = s;
        }
        __syncthreads();
        int carry = s_carry;
        int woff  = wid ? warpsums[wid - 1] : 0;
        int excl  = carry + woff + incl - v;
        if (i < n) { g_row[i] = excl; g_cur[i] = excl; }
        __syncthreads();
        if (tid == 1023) s_carry = carry + warpsums[31];
        __syncthreads();
    }
    if (threadIdx.x == 0) g_row[n] = s_carry;
}

// ---------------- 4. scatter edges into CSR --------------------------------
__global__ void scatter_kernel(const int* __restrict__ src,
                               const int* __restrict__ dst, int e) {
    int i = blockIdx.x * blockDim.x + threadIdx.x;
    if (i < e) {
        int p = atomicAdd(&g_cur[dst[i]], 1);
        g_csr[p] = src[i];
    }
}

// ---------------- 5. per-node mean aggregation (1 warp / node) -------------
__global__ void gather_mean_kernel(const float4* __restrict__ feat, int n) {
    int gw   = (blockIdx.x * blockDim.x + threadIdx.x) >> 5;
    int lane = threadIdx.x & 31;
    if (gw >= n) return;
    int s = g_row[gw], e = g_row[gw + 1];
    float4 acc = make_float4(0.f, 0.f, 0.f, 0.f);
    #pragma unroll 4
    for (int i = s; i < e; i++) {
        int src = g_csr[i];                       // broadcast load (same addr all lanes)
        float4 v = feat[(size_t)src * D4 + lane]; // 512B coalesced per warp
        acc.x += v.x; acc.y += v.y; acc.z += v.z; acc.w += v.w;
    }
    float inv = 1.f / fmaxf((float)(e - s), 1.f);
    acc.x *= inv; acc.y *= inv; acc.z *= inv; acc.w *= inv;
    ((float4*)g_mean)[(size_t)gw * D4 + lane] = acc;
}

// ---------------- 6. GEMM  h = mean @ W + b  (fp32, SMEM A-tile) -----------
// block = 256 threads, tile = 64 rows x 128 cols, thread micro-tile 8x4
__global__ void gemm_kernel(const float* __restrict__ W,
                            const float* __restrict__ bias, int n) {
    __shared__ float sA[64 * D];                  // 32 KB
    int tid  = threadIdx.x;
    int row0 = blockIdx.x * 64;
    const float4* A4  = (const float4*)g_mean;
    float4*       sA4 = (float4*)sA;
    for (int t = tid; t < 64 * D4; t += 256) {
        int r = t >> 5, c = t & 31;
        sA4[t] = (row0 + r < n) ? A4[(size_t)(row0 + r) * D4 + c]
                                : make_float4(0.f, 0.f, 0.f, 0.f);
    }
    __syncthreads();

    int cg = tid & 31, rg = tid >> 5;             // col group (x4), row group (x8)
    float acc[8][4];
    #pragma unroll
    for (int i = 0; i < 8; i++) { acc[i][0]=0.f; acc[i][1]=0.f; acc[i][2]=0.f; acc[i][3]=0.f; }

    const float4* W4 = (const float4*)W;
    #pragma unroll 8
    for (int k = 0; k < D; k += 4) {
        float4 w0 = W4[(k + 0) * D4 + cg];
        float4 w1 = W4[(k + 1) * D4 + cg];
        float4 w2 = W4[(k + 2) * D4 + cg];
        float4 w3 = W4[(k + 3) * D4 + cg];
        #pragma unroll
        for (int i = 0; i < 8; i++) {
            float4 a = *(const float4*)&sA[(rg * 8 + i) * D + k];
            acc[i][0] += a.x * w0.x; acc[i][1] += a.x * w0.y; acc[i][2] += a.x * w0.z; acc[i][3] += a.x * w0.w;
            acc[i][0] += a.y * w1.x; acc[i][1] += a.y * w1.y; acc[i][2] += a.y * w1.z; acc[i][3] += a.y * w1.w;
            acc[i][0] += a.z * w2.x; acc[i][1] += a.z * w2.y; acc[i][2] += a.z * w2.z; acc[i][3] += a.z * w2.w;
            acc[i][0] += a.w * w3.x; acc[i][1] += a.w * w3.y; acc[i][2] += a.w * w3.z; acc[i][3] += a.w * w3.w;
        }
    }

    float4 bb = ((const float4*)bias)[cg];
    #pragma unroll
    for (int i = 0; i < 8; i++) {
        int r = row0 + rg * 8 + i;
        if (r < n) {
            float4 o;
            o.x = acc[i][0] + bb.x; o.y = acc[i][1] + bb.y;
            o.z = acc[i][2] + bb.z; o.w = acc[i][3] + bb.w;
            ((float4*)g_h)[(size_t)r * D4 + cg] = o;
        }
    }
}

// ---------------- 7. column statistics -------------------------------------
__global__ void stats_kernel(int n) {
    int j = threadIdx.x;                           // 128 threads: one column each
    float s = 0.f, s2 = 0.f;
    for (int r = blockIdx.x; r < n; r += gridDim.x) {
        float v = g_h[(size_t)r * D + j];
        s += v; s2 += v * v;
    }
    atomicAdd(&g_colsum[j], s);
    atomicAdd(&g_colsum2[j], s2);
}

// ---------------- 8. fold stats into scale/shift ---------------------------
__global__ void params_kernel(const float* __restrict__ gamma,
                              const float* __restrict__ beta, float inv_n) {
    int j = threadIdx.x;
    float mu  = g_colsum[j]  * inv_n;
    float var = g_colsum2[j] * inv_n - mu * mu;
    float sc  = gamma[j] * rsqrtf(var + EPSV);
    g_scale[j] = sc;
    g_shift[j] = beta[j] - mu * sc;
}

// ---------------- 9. finalize: out = feature + relu(h*scale + shift) -------
__global__ void finalize_kernel(const float4* __restrict__ feat,
                                float4* __restrict__ out, int n4) {
    __shared__ float4 ssc[D4], ssh[D4];
    if (threadIdx.x < D4) {
        ssc[threadIdx.x] = ((const float4*)g_scale)[threadIdx.x];
        ssh[threadIdx.x] = ((const float4*)g_shift)[threadIdx.x];
    }
    __syncthreads();
    const float4* H4 = (const float4*)g_h;
    for (int i = blockIdx.x * blockDim.x + threadIdx.x; i < n4;
         i += gridDim.x * blockDim.x) {
        int c = i & (D4 - 1);
        float4 h = H4[i], f = feat[i], sc = ssc[c], sh = ssh[c];
        float4 o;
        o.x = f.x + fmaxf(h.x * sc.x + sh.x, 0.f);
        o.y = f.y + fmaxf(h.y * sc.y + sh.y, 0.f);
        o.z = f.z + fmaxf(h.z * sc.z + sh.z, 0.f);
        o.w = f.w + fmaxf(h.w * sc.w + sh.w, 0.f);
        out[i] = o;
    }
}

// ---------------- launch ----------------------------------------------------
extern "C" void kernel_launch(void* const* d_in, const int* in_sizes, int n_in,
                              void* d_out, int out_size) {
    const float* feature = (const float*)d_in[0];
    const int*   src     = (const int*)d_in[1];
    const int*   dst     = (const int*)d_in[2];
    const float* W       = (const float*)d_in[3];
    const float* b       = (const float*)d_in[4];
    const float* gamma   = (const float*)d_in[5];
    const float* beta    = (const float*)d_in[6];
    float*       out     = (float*)d_out;

    int n = in_sizes[0] / D;       // 100000 nodes
    int e = in_sizes[1];           // 3200000 edges
    int n4 = n * D4;               // float4 elements of [N, D]

    zero_kernel<<<(n + 255) / 256, 256>>>(n);
    hist_kernel<<<(e + 255) / 256, 256>>>(dst, e);
    scan_kernel<<<1, 1024>>>(n);
    scatter_kernel<<<(e + 255) / 256, 256>>>(src, dst, e);

    int warps = n;                 // one warp per node
    gather_mean_kernel<<<(warps * 32 + 255) / 256, 256>>>((const float4*)feature, n);

    gemm_kernel<<<(n + 63) / 64, 256>>>(W, b, n);

    stats_kernel<<<512, D>>>(n);
    params_kernel<<<1, D>>>(gamma, beta, 1.f / (float)n);

    finalize_kernel<<<(n4 + 255) / 256, 256>>>((const float4*)feature, (float4*)out, n4);
}

// round 2
// speedup vs baseline: 1.5196x; 1.5196x over previous
#include <cuda_runtime.h>
#include <cuda_fp16.h>

#define D       128
#define D4      32          // D/4 float4s per row
#define DH2     64          // D/2 half2 per row
#define N_MAX   100000
#define E_MAX   3200000
#define EPSV    1e-5f
#define SCAN_B  1024

// ---------------- scratch (static device globals) --------------------------
__device__ int    g_deg[N_MAX];
__device__ int    g_row[N_MAX + 1];
__device__ int    g_cur[N_MAX];
__device__ int    g_csr[E_MAX];
__device__ int    g_part[256];          // block partial sums for scan
__device__ __half g_featH[(size_t)N_MAX * D];
__device__ float  g_mean[(size_t)N_MAX * D];
__device__ float  g_h[(size_t)N_MAX * D];
__device__ float  g_colsum[D];
__device__ float  g_colsum2[D];
__device__ float  g_scale[D];
__device__ float  g_shift[D];

// ---------------- 1. zero accumulators -------------------------------------
__global__ void zero_kernel(int n) {
    int i = blockIdx.x * blockDim.x + threadIdx.x;
    if (i < n) g_deg[i] = 0;
    if (i < D) { g_colsum[i] = 0.f; g_colsum2[i] = 0.f; }
}

// ---------------- 2. degree histogram (int4 edges) --------------------------
__global__ void hist_kernel(const int* __restrict__ dst, int e) {
    int i4 = blockIdx.x * blockDim.x + threadIdx.x;
    int base = i4 * 4;
    if (base + 3 < e) {
        int4 d = *(const int4*)(dst + base);
        atomicAdd(&g_deg[d.x], 1);
        atomicAdd(&g_deg[d.y], 1);
        atomicAdd(&g_deg[d.z], 1);
        atomicAdd(&g_deg[d.w], 1);
    } else {
        for (int j = base; j < e; j++) atomicAdd(&g_deg[dst[j]], 1);
    }
}

// ---------------- 3a. per-block sums of deg ---------------------------------
__global__ void scanA_kernel(int n) {
    __shared__ int ws[32];
    int i = blockIdx.x * SCAN_B + threadIdx.x;
    int v = (i < n) ? g_deg[i] : 0;
    #pragma unroll
    for (int off = 16; off > 0; off >>= 1) v += __shfl_down_sync(0xffffffffu, v, off);
    int lane = threadIdx.x & 31, wid = threadIdx.x >> 5;
    if (lane == 0) ws[wid] = v;
    __syncthreads();
    if (wid == 0) {
        int s = (lane < SCAN_B / 32) ? ws[lane] : 0;
        #pragma unroll
        for (int off = 16; off > 0; off >>= 1) s += __shfl_down_sync(0xffffffffu, s, off);
        if (lane == 0) g_part[blockIdx.x] = s;
    }
}

// ---------------- 3b. exclusive scan of partials (<=128) --------------------
__global__ void scanB_kernel(int nb, int n) {
    __shared__ int ws[4];
    int lane = threadIdx.x & 31, wid = threadIdx.x >> 5;
    int v = (threadIdx.x < nb) ? g_part[threadIdx.x] : 0;
    int incl = v;
    #pragma unroll
    for (int off = 1; off < 32; off <<= 1) {
        int t = __shfl_up_sync(0xffffffffu, incl, off);
        if (lane >= off) incl += t;
    }
    if (lane == 31) ws[wid] = incl;
    __syncthreads();
    int woff = 0;
    for (int w = 0; w < wid; w++) woff += ws[w];
    if (threadIdx.x < nb) g_part[threadIdx.x] = woff + incl - v;
    if (threadIdx.x == 127) g_row[n] = woff + incl;   // total
}

// ---------------- 3c. apply: local scan + block offset ----------------------
__global__ void scanC_kernel(int n) {
    __shared__ int ws[32];
    int i = blockIdx.x * SCAN_B + threadIdx.x;
    int lane = threadIdx.x & 31, wid = threadIdx.x >> 5;
    int v = (i < n) ? g_deg[i] : 0;
    int incl = v;
    #pragma unroll
    for (int off = 1; off < 32; off <<= 1) {
        int t = __shfl_up_sync(0xffffffffu, incl, off);
        if (lane >= off) incl += t;
    }
    if (lane == 31) ws[wid] = incl;
    __syncthreads();
    if (wid == 0) {
        int s = ws[lane];
        #pragma unroll
        for (int off = 1; off < 32; off <<= 1) {
            int t = __shfl_up_sync(0xffffffffu, s, off);
            if (lane >= off) s += t;
        }
        ws[lane] = s;
    }
    __syncthreads();
    int woff = wid ? ws[wid - 1] : 0;
    int excl = g_part[blockIdx.x] + woff + incl - v;
    if (i < n) { g_row[i] = excl; g_cur[i] = excl; }
}

// ---------------- 4. scatter edges into CSR (int4) --------------------------
__global__ void scatter_kernel(const int* __restrict__ src,
                               const int* __restrict__ dst, int e) {
    int i4 = blockIdx.x * blockDim.x + threadIdx.x;
    int base = i4 * 4;
    if (base + 3 < e) {
        int4 d = *(const int4*)(dst + base);
        int4 s = *(const int4*)(src + base);
        g_csr[atomicAdd(&g_cur[d.x], 1)] = s.x;
        g_csr[atomicAdd(&g_cur[d.y], 1)] = s.y;
        g_csr[atomicAdd(&g_cur[d.z], 1)] = s.z;
        g_csr[atomicAdd(&g_cur[d.w], 1)] = s.w;
    } else {
        for (int j = base; j < e; j++)
            g_csr[atomicAdd(&g_cur[dst[j]], 1)] = src[j];
    }
}

// ---------------- 5. convert feature to fp16 --------------------------------
__global__ void tohalf_kernel(const float4* __restrict__ feat, int tot8) {
    int i = blockIdx.x * blockDim.x + threadIdx.x;     // one per 8 floats
    if (i >= tot8) return;
    float4 a = feat[2 * i], b = feat[2 * i + 1];
    __half2 h0 = __floats2half2_rn(a.x, a.y);
    __half2 h1 = __floats2half2_rn(a.z, a.w);
    __half2 h2 = __floats2half2_rn(b.x, b.y);
    __half2 h3 = __floats2half2_rn(b.z, b.w);
    uint4 o;
    o.x = *(unsigned*)&h0; o.y = *(unsigned*)&h1;
    o.z = *(unsigned*)&h2; o.w = *(unsigned*)&h3;
    ((uint4*)g_featH)[i] = o;
}

// ---------------- 6. per-node mean aggregation (1 warp/node, fp16 in) -------
__global__ void gather_mean_kernel(int n) {
    int gw   = (blockIdx.x * blockDim.x + threadIdx.x) >> 5;
    int lane = threadIdx.x & 31;
    if (gw >= n) return;
    int s = g_row[gw], e = g_row[gw + 1];
    const uint2* F = (const uint2*)g_featH;            // 4 halfs per lane
    float a0 = 0.f, a1 = 0.f, a2 = 0.f, a3 = 0.f;
    #pragma unroll 4
    for (int i = s; i < e; i++) {
        int sr = g_csr[i];                              // broadcast
        uint2 v = __ldg(&F[(size_t)sr * 32 + lane]);    // 256B coalesced / warp
        float2 f0 = __half22float2(*(__half2*)&v.x);
        float2 f1 = __half22float2(*(__half2*)&v.y);
        a0 += f0.x; a1 += f0.y; a2 += f1.x; a3 += f1.y;
    }
    float inv = 1.f / fmaxf((float)(e - s), 1.f);
    float4 o = make_float4(a0 * inv, a1 * inv, a2 * inv, a3 * inv);
    ((float4*)g_mean)[(size_t)gw * D4 + lane] = o;
}

// ---------------- 7. GEMM h = mean @ W + b, fused column stats --------------
// block = 256 threads, tile = 64 rows x 128 cols, thread micro-tile 8x4
__global__ void gemm_kernel(const float* __restrict__ W,
                            const float* __restrict__ bias, int n) {
    __shared__ float sA[64 * D];                        // 32 KB
    __shared__ float s_sum[D], s_sum2[D];
    int tid  = threadIdx.x;
    int row0 = blockIdx.x * 64;
    const float4* A4  = (const float4*)g_mean;
    float4*       sA4 = (float4*)sA;
    for (int t = tid; t < 64 * D4; t += 256) {
        int r = t >> 5, c = t & 31;
        sA4[t] = (row0 + r < n) ? A4[(size_t)(row0 + r) * D4 + c]
                                : make_float4(0.f, 0.f, 0.f, 0.f);
    }
    if (tid < D) { s_sum[tid] = 0.f; s_sum2[tid] = 0.f; }
    __syncthreads();

    int cg = tid & 31, rg = tid >> 5;
    float acc[8][4];
    #pragma unroll
    for (int i = 0; i < 8; i++) { acc[i][0]=0.f; acc[i][1]=0.f; acc[i][2]=0.f; acc[i][3]=0.f; }

    const float4* W4 = (const float4*)W;
    #pragma unroll 8
    for (int k = 0; k < D; k += 4) {
        float4 w0 = W4[(k + 0) * D4 + cg];
        float4 w1 = W4[(k + 1) * D4 + cg];
        float4 w2 = W4[(k + 2) * D4 + cg];
        float4 w3 = W4[(k + 3) * D4 + cg];
        #pragma unroll
        for (int i = 0; i < 8; i++) {
            float4 a = *(const float4*)&sA[(rg * 8 + i) * D + k];
            acc[i][0] += a.x * w0.x; acc[i][1] += a.x * w0.y; acc[i][2] += a.x * w0.z; acc[i][3] += a.x * w0.w;
            acc[i][0] += a.y * w1.x; acc[i][1] += a.y * w1.y; acc[i][2] += a.y * w1.z; acc[i][3] += a.y * w1.w;
            acc[i][0] += a.z * w2.x; acc[i][1] += a.z * w2.y; acc[i][2] += a.z * w2.z; acc[i][3] += a.z * w2.w;
            acc[i][0] += a.w * w3.x; acc[i][1] += a.w * w3.y; acc[i][2] += a.w * w3.z; acc[i][3] += a.w * w3.w;
        }
    }

    float4 bb = ((const float4*)bias)[cg];
    float ls0=0.f, ls1=0.f, ls2=0.f, ls3=0.f;
    float lq0=0.f, lq1=0.f, lq2=0.f, lq3=0.f;
    #pragma unroll
    for (int i = 0; i < 8; i++) {
        int r = row0 + rg * 8 + i;
        if (r < n) {
            float4 o;
            o.x = acc[i][0] + bb.x; o.y = acc[i][1] + bb.y;
            o.z = acc[i][2] + bb.z; o.w = acc[i][3] + bb.w;
            ((float4*)g_h)[(size_t)r * D4 + cg] = o;
            ls0 += o.x; ls1 += o.y; ls2 += o.z; ls3 += o.w;
            lq0 += o.x*o.x; lq1 += o.y*o.y; lq2 += o.z*o.z; lq3 += o.w*o.w;
        }
    }
    atomicAdd(&s_sum[4*cg+0], ls0);  atomicAdd(&s_sum[4*cg+1], ls1);
    atomicAdd(&s_sum[4*cg+2], ls2);  atomicAdd(&s_sum[4*cg+3], ls3);
    atomicAdd(&s_sum2[4*cg+0], lq0); atomicAdd(&s_sum2[4*cg+1], lq1);
    atomicAdd(&s_sum2[4*cg+2], lq2); atomicAdd(&s_sum2[4*cg+3], lq3);
    __syncthreads();
    if (tid < D) {
        atomicAdd(&g_colsum[tid],  s_sum[tid]);
        atomicAdd(&g_colsum2[tid], s_sum2[tid]);
    }
}

// ---------------- 8. fold stats into scale/shift -----------------------------
__global__ void params_kernel(const float* __restrict__ gamma,
                              const float* __restrict__ beta, float inv_n) {
    int j = threadIdx.x;
    float mu  = g_colsum[j]  * inv_n;
    float var = g_colsum2[j] * inv_n - mu * mu;
    float sc  = gamma[j] * rsqrtf(var + EPSV);
    g_scale[j] = sc;
    g_shift[j] = beta[j] - mu * sc;
}

// ---------------- 9. finalize: out = feature + relu(h*scale + shift) --------
__global__ void finalize_kernel(const float4* __restrict__ feat,
                                float4* __restrict__ out, int n4) {
    __shared__ float4 ssc[D4], ssh[D4];
    if (threadIdx.x < D4) {
        ssc[threadIdx.x] = ((const float4*)g_scale)[threadIdx.x];
        ssh[threadIdx.x] = ((const float4*)g_shift)[threadIdx.x];
    }
    __syncthreads();
    const float4* H4 = (const float4*)g_h;
    for (int i = blockIdx.x * blockDim.x + threadIdx.x; i < n4;
         i += gridDim.x * blockDim.x) {
        int c = i & (D4 - 1);
        float4 h = H4[i], f = feat[i], sc = ssc[c], sh = ssh[c];
        float4 o;
        o.x = f.x + fmaxf(h.x * sc.x + sh.x, 0.f);
        o.y = f.y + fmaxf(h.y * sc.y + sh.y, 0.f);
        o.z = f.z + fmaxf(h.z * sc.z + sh.z, 0.f);
        o.w = f.w + fmaxf(h.w * sc.w + sh.w, 0.f);
        out[i] = o;
    }
}

// ---------------- launch -----------------------------------------------------
extern "C" void kernel_launch(void* const* d_in, const int* in_sizes, int n_in,
                              void* d_out, int out_size) {
    const float* feature = (const float*)d_in[0];
    const int*   src     = (const int*)d_in[1];
    const int*   dst     = (const int*)d_in[2];
    const float* W       = (const float*)d_in[3];
    const float* b       = (const float*)d_in[4];
    const float* gamma   = (const float*)d_in[5];
    const float* beta    = (const float*)d_in[6];
    float*       out     = (float*)d_out;

    int n  = in_sizes[0] / D;        // 100000 nodes
    int e  = in_sizes[1];            // 3200000 edges
    int n4 = n * D4;
    int nb = (n + SCAN_B - 1) / SCAN_B;   // <= 128 scan blocks

    zero_kernel<<<(n + 255) / 256, 256>>>(n);
    hist_kernel<<<((e + 3) / 4 + 255) / 256, 256>>>(dst, e);
    scanA_kernel<<<nb, SCAN_B>>>(n);
    scanB_kernel<<<1, 128>>>(nb, n);
    scanC_kernel<<<nb, SCAN_B>>>(n);
    scatter_kernel<<<((e + 3) / 4 + 255) / 256, 256>>>(src, dst, e);

    int tot8 = n * D / 8;
    tohalf_kernel<<<(tot8 + 255) / 256, 256>>>((const float4*)feature, tot8);

    gather_mean_kernel<<<(n * 32 + 255) / 256, 256>>>(n);

    gemm_kernel<<<(n + 63) / 64, 256>>>(W, b, n);

    params_kernel<<<1, D>>>(gamma, beta, 1.f / (float)n);

    finalize_kernel<<<(n4 + 255) / 256, 256>>>((const float4*)feature, (float4*)out, n4);
}